// round 1
// baseline (speedup 1.0000x reference)
#include <cuda_runtime.h>

// Problem constants
#define BATCH 16
#define CH    128
#define HH    56
#define WW    56
#define HWSZ  3136            // 56*56
#define NPIX  50176           // 16*3136
#define XSTRB 401408          // 128*3136 (batch stride in NCHW)
#define NELEM 6422528         // 16*128*56*56

// ---------------- device scratch (no allocations allowed) ----------------
__device__ float g_wq1[9 * 128 * 128];   // quantized weights, layout [k][c][o]
__device__ float g_wq2[9 * 128 * 128];
__device__ float g_t1[128 * NPIX];       // conv1 pre-BN output, layout [c][n], n=b*3136+hw
__device__ float g_t2[128 * NPIX];       // conv2 pre-BN output
__device__ float g_sum1[128], g_sumsq1[128];
__device__ float g_sum2[128], g_sumsq2[128];
__device__ float g_scale1[128], g_bias1[128];
__device__ float g_scale2[128], g_bias2[128];

// ---------------- prep: quantize weights (LSQ, 3-bit) + zero stats ----------------
__global__ void prep_kernel(const float* __restrict__ w1, const float* __restrict__ wa1,
                            const float* __restrict__ w2, const float* __restrict__ wa2)
{
    if (blockIdx.x == 0 && threadIdx.x < 128) {
        int t = threadIdx.x;
        g_sum1[t] = 0.f; g_sumsq1[t] = 0.f;
        g_sum2[t] = 0.f; g_sumsq2[t] = 0.f;
    }
    int idx = blockIdx.x * blockDim.x + threadIdx.x;
    if (idx < 2 * 9 * 128 * 128) {
        int layer = idx / (9 * 128 * 128);
        int r = idx - layer * (9 * 128 * 128);
        int k = r >> 14;
        int o = (r >> 7) & 127;
        int c = r & 127;
        const float* w  = layer ? w2  : w1;
        const float* wa = layer ? wa2 : wa1;
        float alpha = wa[k];
        // lsq: round(clip(w/alpha, -4, 3)) * alpha   (NBITS=3)
        float v = __fdiv_rn(w[(k << 14) + (o << 7) + c], alpha);
        v = fminf(fmaxf(v, -4.f), 3.f);
        float q = __fmul_rn(rintf(v), alpha);
        float* dst = layer ? g_wq2 : g_wq1;
        dst[(k << 14) + (c << 7) + o] = q;   // transpose to [k][c][o]
    }
}

// ---------------- conv: 9-tap split conv with per-tap psum LSQ (8-bit) ----------------
// Block: 64 pixels x 128 output channels. Threads 256, each computes 8o x 4n.
// LAYER 1: input = x (NCHW). LAYER 2: input = g_t1 ([c][n]) with BN1+ReLU applied on load.
template <int LAYER>
__global__ __launch_bounds__(256, 2)
void conv_kernel(const float* __restrict__ in, const float* __restrict__ pa)
{
    __shared__ float sA[16][64];    // [c_chunk][n]
    __shared__ float sB[16][128];   // [c_chunk][o]
    __shared__ float sRed[2][128];  // per-channel block partial sum / sumsq

    const int t  = threadIdx.x;
    const int n0 = blockIdx.x << 6;

    // this thread's global-load pixel column
    const int nl = t & 63;
    const int n  = n0 + nl;
    const int b  = n / HWSZ;
    const int hw = n - b * HWSZ;
    const int h  = hw / WW;
    const int w  = hw - h * WW;
    const int cload = t >> 6;       // base c row for A loads (0..3)

    // compute-tile coordinates
    const int og = t & 15;          // o = og*8 + i
    const int ng = t >> 4;          // n = n0 + ng*4 + j

    const float* wq  = (LAYER == 1) ? g_wq1 : g_wq2;
    const float* src = (LAYER == 1) ? in : g_t1;

    float acc[8][4];
#pragma unroll
    for (int i = 0; i < 8; i++)
#pragma unroll
        for (int j = 0; j < 4; j++) acc[i][j] = 0.f;

#pragma unroll 1
    for (int k = 0; k < 9; k++) {
        // view k: xs[...,h,w] = x[..., h + k%3 - 1, w + k/3 - 1] (zero-padded)
        const int di = k % 3 - 1;
        const int dj = k / 3 - 1;
        const int hh = h + di, ww2 = w + dj;
        const bool valid = (hh >= 0) && (hh < HH) && (ww2 >= 0) && (ww2 < WW);
        int base;
        if (LAYER == 1) base = b * XSTRB + hh * WW + ww2;  // + c*HWSZ
        else            base = b * HWSZ  + hh * WW + ww2;  // + c*NPIX

        float psum[8][4];
#pragma unroll
        for (int i = 0; i < 8; i++)
#pragma unroll
            for (int j = 0; j < 4; j++) psum[i][j] = 0.f;

#pragma unroll 1
        for (int cc = 0; cc < 128; cc += 16) {
            __syncthreads();
            // --- load A tile: 16c x 64n ---
#pragma unroll
            for (int i = 0; i < 4; i++) {
                int cl = cload + (i << 2);
                int c  = cc + cl;
                float v = 0.f;
                if (valid) {
                    if (LAYER == 1) {
                        v = __ldg(src + base + c * HWSZ);
                    } else {
                        float u = __ldg(src + base + c * NPIX);
                        v = fmaxf(fmaf(u, g_scale1[c], g_bias1[c]), 0.f);  // BN1 + ReLU
                    }
                }
                sA[cl][nl] = v;
            }
            // --- load B tile: 16c x 128o ---
            const float* wk = wq + (k << 14) + (cc << 7);
#pragma unroll
            for (int i = 0; i < 8; i++) {
                int cl = (t >> 7) + (i << 1);
                sB[cl][t & 127] = wk[(cl << 7) + (t & 127)];
            }
            __syncthreads();
            // --- FMA core ---
#pragma unroll
            for (int c = 0; c < 16; c++) {
                float4 av = *reinterpret_cast<const float4*>(&sA[c][ng << 2]);
                float4 b0 = *reinterpret_cast<const float4*>(&sB[c][og << 3]);
                float4 b1 = *reinterpret_cast<const float4*>(&sB[c][(og << 3) + 4]);
                float a[4]  = {av.x, av.y, av.z, av.w};
                float bb[8] = {b0.x, b0.y, b0.z, b0.w, b1.x, b1.y, b1.z, b1.w};
#pragma unroll
                for (int i = 0; i < 8; i++)
#pragma unroll
                    for (int j = 0; j < 4; j++)
                        psum[i][j] = fmaf(bb[i], a[j], psum[i][j]);
            }
        }
        // --- per-tap partial-sum LSQ (8-bit): round(clip(ps/pa,-128,127))*pa ---
        const float pak = pa[k];
#pragma unroll
        for (int i = 0; i < 8; i++)
#pragma unroll
            for (int j = 0; j < 4; j++) {
                float v = __fdiv_rn(psum[i][j], pak);
                v = fminf(fmaxf(v, -128.f), 127.f);
                acc[i][j] = __fadd_rn(acc[i][j], __fmul_rn(rintf(v), pak));
            }
    }

    // ---------------- epilogue: store [c][n] + per-channel stats ----------------
    float* outT = (LAYER == 1) ? g_t1 : g_t2;
    float* ssum = (LAYER == 1) ? g_sum1 : g_sum2;
    float* ssq  = (LAYER == 1) ? g_sumsq1 : g_sumsq2;

    if (t < 128) { sRed[0][t] = 0.f; sRed[1][t] = 0.f; }
    __syncthreads();

#pragma unroll
    for (int i = 0; i < 8; i++) {
        int o = (og << 3) + i;
        float4 vv = make_float4(acc[i][0], acc[i][1], acc[i][2], acc[i][3]);
        *reinterpret_cast<float4*>(&outT[o * NPIX + n0 + (ng << 2)]) = vv;
        float s = acc[i][0] + acc[i][1] + acc[i][2] + acc[i][3];
        float q = acc[i][0] * acc[i][0] + acc[i][1] * acc[i][1] +
                  acc[i][2] * acc[i][2] + acc[i][3] * acc[i][3];
        atomicAdd(&sRed[0][o], s);
        atomicAdd(&sRed[1][o], q);
    }
    __syncthreads();
    if (t < 128) {
        atomicAdd(&ssum[t], sRed[0][t]);
        atomicAdd(&ssq[t],  sRed[1][t]);
    }
}

// ---------------- BN finalize: scale = g/sqrt(var+eps), bias = b - mean*scale ----------------
__global__ void bn_finalize_kernel(int layer, const float* __restrict__ g, const float* __restrict__ bv)
{
    int c = threadIdx.x;
    if (c < 128) {
        float sum = (layer == 1) ? g_sum1[c]   : g_sum2[c];
        float sq  = (layer == 1) ? g_sumsq1[c] : g_sumsq2[c];
        float m   = __fdiv_rn(sum, (float)NPIX);
        float var = fmaxf(__fdiv_rn(sq, (float)NPIX) - m * m, 0.f);
        float s   = __fdiv_rn(g[c], sqrtf(var + 1e-5f));
        float bb  = bv[c] - m * s;
        if (layer == 1) { g_scale1[c] = s; g_bias1[c] = bb; }
        else            { g_scale2[c] = s; g_bias2[c] = bb; }
    }
}

// ---------------- final: out = relu(bn2(t2) + identity), NCHW ----------------
__global__ void final_kernel(const float* __restrict__ x, float* __restrict__ out)
{
    int idx = blockIdx.x * blockDim.x + threadIdx.x;   // float4 index
    if (idx >= NELEM / 4) return;
    int e  = idx << 2;
    int b  = e / XSTRB;
    int r  = e - b * XSTRB;
    int c  = r / HWSZ;
    int hw = r - c * HWSZ;
    float4 xv = *reinterpret_cast<const float4*>(x + e);
    float4 tv = *reinterpret_cast<const float4*>(&g_t2[c * NPIX + b * HWSZ + hw]);
    float s = g_scale2[c], bb = g_bias2[c];
    float4 ov;
    ov.x = fmaxf(fmaf(tv.x, s, bb) + xv.x, 0.f);
    ov.y = fmaxf(fmaf(tv.y, s, bb) + xv.y, 0.f);
    ov.z = fmaxf(fmaf(tv.z, s, bb) + xv.z, 0.f);
    ov.w = fmaxf(fmaf(tv.w, s, bb) + xv.w, 0.f);
    *reinterpret_cast<float4*>(out + e) = ov;
}

// ---------------- launch ----------------
extern "C" void kernel_launch(void* const* d_in, const int* in_sizes, int n_in,
                              void* d_out, int out_size)
{
    const float* x   = (const float*)d_in[0];
    const float* w1  = (const float*)d_in[1];
    const float* wa1 = (const float*)d_in[2];
    const float* pa1 = (const float*)d_in[3];
    const float* g1  = (const float*)d_in[4];
    const float* b1  = (const float*)d_in[5];
    const float* w2  = (const float*)d_in[6];
    const float* wa2 = (const float*)d_in[7];
    const float* pa2 = (const float*)d_in[8];
    const float* g2  = (const float*)d_in[9];
    const float* b2  = (const float*)d_in[10];
    float* out = (float*)d_out;

    (void)in_sizes; (void)n_in; (void)out_size;

    // 1) quantize weights (both layers) + zero BN stat accumulators
    prep_kernel<<<1152, 256>>>(w1, wa1, w2, wa2);
    // 2) conv1: x -> g_t1 (pre-BN) + stats
    conv_kernel<1><<<NPIX / 64, 256>>>(x, pa1);
    // 3) BN1 params
    bn_finalize_kernel<<<1, 128>>>(1, g1, b1);
    // 4) conv2: relu(bn1(g_t1)) -> g_t2 (pre-BN) + stats
    conv_kernel<2><<<NPIX / 64, 256>>>(x /*unused*/, pa2);
    // 5) BN2 params
    bn_finalize_kernel<<<1, 128>>>(2, g2, b2);
    // 6) out = relu(bn2(g_t2) + x)
    final_kernel<<<NELEM / 4 / 256, 256>>>(x, out);
}